// round 6
// baseline (speedup 1.0000x reference)
#include <cuda_runtime.h>
#include <cstdint>
#include <cstddef>

// Problem constants (fixed by the dataset)
#define N_TOK   1048576
#define B_SEG   4096
#define D_IN    256
#define H_MLP   128
#define N_TILES (N_TOK / 16)      // 65536 tiles of 16 tokens

// smem: 16 kt * 16 nt * 32 lanes * 16B packed W1 fragments + 128 float2 (b1,W2)
#define BFRAG_ELEMS (16 * 16 * 32)
#define SMEM_BYTES  (BFRAG_ELEMS * 16 + H_MLP * 8)

__device__ int g_start[B_SEG + 1];

// ---------------------------------------------------------------------------
// helpers
// ---------------------------------------------------------------------------
__device__ __forceinline__ uint32_t pack_bf16x2(float hi, float lo) {
    // result = { upper16 = bf16(hi), lower16 = bf16(lo) }
    uint32_t r;
    asm("cvt.rn.bf16x2.f32 %0, %1, %2;" : "=r"(r) : "f"(hi), "f"(lo));
    return r;
}

__device__ __forceinline__ void mma_bf16(float d[4],
                                         uint32_t a0, uint32_t a1, uint32_t a2, uint32_t a3,
                                         uint32_t b0, uint32_t b1) {
    asm volatile(
        "mma.sync.aligned.m16n8k16.row.col.f32.bf16.bf16.f32 "
        "{%0,%1,%2,%3}, {%4,%5,%6,%7}, {%8,%9}, {%0,%1,%2,%3};\n"
        : "+f"(d[0]), "+f"(d[1]), "+f"(d[2]), "+f"(d[3])
        : "r"(a0), "r"(a1), "r"(a2), "r"(a3), "r"(b0), "r"(b1));
}

__device__ __forceinline__ float fast_tanh(float v) {
    // tanh(v) = 1 - 2/(exp(2v)+1); saturates correctly at +/-inf of the exp.
    float e = __expf(2.0f * v);
    return 1.0f - __fdividef(2.0f, e + 1.0f);
}

// ---------------------------------------------------------------------------
// Pass 0: segment start offsets via binary search (ids are sorted)
// ---------------------------------------------------------------------------
__global__ void find_starts_kernel(const int* __restrict__ seg) {
    int b = blockIdx.x * blockDim.x + threadIdx.x;
    if (b > B_SEG) return;
    if (b == B_SEG) { g_start[B_SEG] = N_TOK; return; }
    int lo = 0, hi = N_TOK;
    while (lo < hi) {
        int mid = (lo + hi) >> 1;
        if (seg[mid] < b) lo = mid + 1; else hi = mid;
    }
    g_start[b] = lo;
}

// ---------------------------------------------------------------------------
// Pass 1: s[n] = tanh(x @ W1 + b1) @ W2 + b2   via split-bf16 tensor-core GEMM
// One warp computes a 16-token x 128-hidden tile; K=256 in 16 steps.
// W1 fragments (hi+lo bf16 split) pre-packed in smem in mma B-fragment layout.
// ---------------------------------------------------------------------------
__global__ __launch_bounds__(512, 1)
void logits_kernel(const float* __restrict__ x,
                   const float* __restrict__ W1,
                   const float* __restrict__ b1,
                   const float* __restrict__ W2,
                   const float* __restrict__ b2,
                   float* __restrict__ s_out) {
    extern __shared__ unsigned char smem_raw[];
    uint4*  bfrag = reinterpret_cast<uint4*>(smem_raw);
    float2* pw    = reinterpret_cast<float2*>(smem_raw + BFRAG_ELEMS * 16);

    const int tid = threadIdx.x;

    // --- pack W1 (hi/lo bf16 split) into B-fragment layout ---
    for (int e = tid; e < BFRAG_ELEMS; e += 512) {
        int kt = e >> 9;
        int nt = (e >> 5) & 15;
        int ln = e & 31;
        int k0 = kt * 16 + (ln & 3) * 2;      // k index of b0
        int nn = nt * 8 + (ln >> 2);          // n index
        float v0 = W1[(k0    ) * H_MLP + nn];
        float v1 = W1[(k0 + 1) * H_MLP + nn];
        float v2 = W1[(k0 + 8) * H_MLP + nn];
        float v3 = W1[(k0 + 9) * H_MLP + nn];
        uint32_t h0 = pack_bf16x2(v1, v0);
        uint32_t h1 = pack_bf16x2(v3, v2);
        float r0 = v0 - __uint_as_float(h0 << 16);
        float r1 = v1 - __uint_as_float(h0 & 0xffff0000u);
        float r2 = v2 - __uint_as_float(h1 << 16);
        float r3 = v3 - __uint_as_float(h1 & 0xffff0000u);
        uint32_t l0 = pack_bf16x2(r1, r0);
        uint32_t l1 = pack_bf16x2(r3, r2);
        bfrag[e] = make_uint4(h0, h1, l0, l1);
    }
    for (int n = tid; n < H_MLP; n += 512)
        pw[n] = make_float2(b1[n], W2[n]);
    const float bias2 = b2[0];
    __syncthreads();

    const int warp  = tid >> 5;
    const int lane  = tid & 31;
    const int g     = lane >> 2;          // row within groups
    const int cbase = (lane & 3) * 2;     // col pair base

    for (int tile = blockIdx.x * 16 + warp; tile < N_TILES; tile += gridDim.x * 16) {
        const float* xr0 = x + (size_t)(tile * 16 + g) * D_IN;
        const float* xr1 = xr0 + 8 * D_IN;

        float acc[64];
#pragma unroll
        for (int i = 0; i < 64; i++) acc[i] = 0.0f;

        // prefetch kt = 0
        float2 q0 = *reinterpret_cast<const float2*>(xr0 + cbase);
        float2 q1 = *reinterpret_cast<const float2*>(xr0 + cbase + 8);
        float2 q2 = *reinterpret_cast<const float2*>(xr1 + cbase);
        float2 q3 = *reinterpret_cast<const float2*>(xr1 + cbase + 8);

#pragma unroll 1
        for (int kt = 0; kt < 16; kt++) {
            float2 c0 = q0, c1 = q1, c2 = q2, c3 = q3;
            if (kt < 15) {
                int c = (kt + 1) * 16 + cbase;
                q0 = *reinterpret_cast<const float2*>(xr0 + c);
                q1 = *reinterpret_cast<const float2*>(xr0 + c + 8);
                q2 = *reinterpret_cast<const float2*>(xr1 + c);
                q3 = *reinterpret_cast<const float2*>(xr1 + c + 8);
            }
            // A fragments: a0=(r0,c..), a1=(r1,c..), a2=(r0,c+8..), a3=(r1,c+8..)
            uint32_t ah0 = pack_bf16x2(c0.y, c0.x);
            uint32_t ah1 = pack_bf16x2(c2.y, c2.x);
            uint32_t ah2 = pack_bf16x2(c1.y, c1.x);
            uint32_t ah3 = pack_bf16x2(c3.y, c3.x);
            uint32_t al0 = pack_bf16x2(c0.y - __uint_as_float(ah0 & 0xffff0000u),
                                       c0.x - __uint_as_float(ah0 << 16));
            uint32_t al1 = pack_bf16x2(c2.y - __uint_as_float(ah1 & 0xffff0000u),
                                       c2.x - __uint_as_float(ah1 << 16));
            uint32_t al2 = pack_bf16x2(c1.y - __uint_as_float(ah2 & 0xffff0000u),
                                       c1.x - __uint_as_float(ah2 << 16));
            uint32_t al3 = pack_bf16x2(c3.y - __uint_as_float(ah3 & 0xffff0000u),
                                       c3.x - __uint_as_float(ah3 << 16));

            const uint4* bp = bfrag + kt * 512 + lane;
#pragma unroll
            for (int nt = 0; nt < 16; nt++) {
                uint4 bb = bp[nt * 32];             // one conflict-free LDS.128
                float* d = &acc[nt * 4];
                mma_bf16(d, ah0, ah1, ah2, ah3, bb.x, bb.y);  // x_hi * W_hi
                mma_bf16(d, al0, al1, al2, al3, bb.x, bb.y);  // x_lo * W_hi
                mma_bf16(d, ah0, ah1, ah2, ah3, bb.z, bb.w);  // x_hi * W_lo
            }
        }

        // epilogue: s = sum_n tanh(h + b1) * W2
        float p0 = 0.0f, p1 = 0.0f;
#pragma unroll
        for (int nt = 0; nt < 16; nt++) {
            int n0 = nt * 8 + cbase;
            float2 w0 = pw[n0];
            float2 w1 = pw[n0 + 1];
            p0 += fast_tanh(acc[nt * 4 + 0] + w0.x) * w0.y;
            p0 += fast_tanh(acc[nt * 4 + 1] + w1.x) * w1.y;
            p1 += fast_tanh(acc[nt * 4 + 2] + w0.x) * w0.y;
            p1 += fast_tanh(acc[nt * 4 + 3] + w1.x) * w1.y;
        }
        p0 += __shfl_xor_sync(0xffffffffu, p0, 1);
        p0 += __shfl_xor_sync(0xffffffffu, p0, 2);
        p1 += __shfl_xor_sync(0xffffffffu, p1, 1);
        p1 += __shfl_xor_sync(0xffffffffu, p1, 2);
        if ((lane & 3) == 0) {
            int r = tile * 16 + g;
            s_out[r]     = p0 + bias2;
            s_out[r + 8] = p1 + bias2;
        }
    }
}

// ---------------------------------------------------------------------------
// Pass 2: per-segment softmax, IN PLACE (s -> attention weights)
// ---------------------------------------------------------------------------
__global__ void softmax_kernel(float* __restrict__ sw) {
    __shared__ float red[8];
    __shared__ float bcast[2];
    const int b   = blockIdx.x;
    const int s0  = g_start[b];
    const int s1  = g_start[b + 1];
    const int tid = threadIdx.x;

    float m = -3.402823466e38f;
    for (int i = s0 + tid; i < s1; i += 256) m = fmaxf(m, sw[i]);
#pragma unroll
    for (int o = 16; o; o >>= 1) m = fmaxf(m, __shfl_xor_sync(0xffffffffu, m, o));
    if ((tid & 31) == 0) red[tid >> 5] = m;
    __syncthreads();
    if (tid == 0) {
        float v = red[0];
#pragma unroll
        for (int i = 1; i < 8; i++) v = fmaxf(v, red[i]);
        bcast[0] = v;
    }
    __syncthreads();
    m = bcast[0];

    float sum = 0.0f;
    for (int i = s0 + tid; i < s1; i += 256) sum += expf(sw[i] - m);
#pragma unroll
    for (int o = 16; o; o >>= 1) sum += __shfl_xor_sync(0xffffffffu, sum, o);
    __syncthreads();
    if ((tid & 31) == 0) red[tid >> 5] = sum;
    __syncthreads();
    if (tid == 0) {
        float v = 0.0f;
#pragma unroll
        for (int i = 0; i < 8; i++) v += red[i];
        bcast[1] = v;
    }
    __syncthreads();
    const float denom = bcast[1];

    for (int i = s0 + tid; i < s1; i += 256)
        sw[i] = expf(sw[i] - m) / denom;
}

// ---------------------------------------------------------------------------
// Pass 3: context[b,:] = sum_{n in segment} w[n] * x[n,:]
// One block per segment, one thread per feature column (perfectly coalesced).
// ---------------------------------------------------------------------------
__global__ void pool_kernel(const float* __restrict__ x,
                            const float* __restrict__ w,
                            float* __restrict__ ctx) {
    const int b  = blockIdx.x;
    const int d  = threadIdx.x;
    const int s0 = g_start[b];
    const int s1 = g_start[b + 1];

    float acc = 0.0f;
    const float* xp = x + (size_t)s0 * D_IN + d;
    int n = s0;
    for (; n + 4 <= s1; n += 4) {
        float w0 = __ldg(w + n);
        float w1 = __ldg(w + n + 1);
        float w2 = __ldg(w + n + 2);
        float w3 = __ldg(w + n + 3);
        acc += w0 * xp[0];
        acc += w1 * xp[D_IN];
        acc += w2 * xp[2 * D_IN];
        acc += w3 * xp[3 * D_IN];
        xp += 4 * D_IN;
    }
    for (; n < s1; n++) {
        acc += __ldg(w + n) * xp[0];
        xp += D_IN;
    }
    ctx[b * D_IN + d] = acc;
}

// ---------------------------------------------------------------------------
// launch: outputs are [context_vectors (B*D)] then [attention_weights (N)]
// ---------------------------------------------------------------------------
extern "C" void kernel_launch(void* const* d_in, const int* in_sizes, int n_in,
                              void* d_out, int out_size) {
    const float* x   = (const float*)d_in[0];
    const int*   seg = (const int*)d_in[1];
    const float* W1  = (const float*)d_in[2];
    const float* b1  = (const float*)d_in[3];
    const float* W2  = (const float*)d_in[4];
    const float* b2  = (const float*)d_in[5];

    float* ctx = (float*)d_out;                       // [B, D]
    float* sw  = ctx + (size_t)B_SEG * D_IN;          // [N] : logits then weights

    cudaFuncSetAttribute(logits_kernel,
                         cudaFuncAttributeMaxDynamicSharedMemorySize, SMEM_BYTES);

    find_starts_kernel<<<(B_SEG + 256) / 256, 256>>>(seg);
    logits_kernel<<<152, 512, SMEM_BYTES>>>(x, W1, b1, W2, b2, sw);
    softmax_kernel<<<B_SEG, 256>>>(sw);
    pool_kernel<<<B_SEG, 256>>>(x, sw, ctx);
}